// round 14
// baseline (speedup 1.0000x reference)
#include <cuda_runtime.h>

#define N_ROWS  8192
#define N_COLS  32000
#define NV4     (N_COLS / 4)      // 8000 float4 per row
#define K2      4915              // int(0.6 * int(1.0 * 8192))
#define THREADS 256
#define HBITS   13
#define NBINS   (1 << HBITS)      // 8192 bins, top-13-bit bucket

// Scratch (device globals — zero-init at load; select kernel restores g_hist)
__device__ unsigned int g_keys[N_ROWS];
__device__ unsigned int g_hist[NBINS];

__device__ __forceinline__ unsigned int key_of(float f) {
    unsigned int u = __float_as_uint(f);
    return u ^ ((u & 0x80000000u) ? 0xFFFFFFFFu : 0x80000000u);
}
__device__ __forceinline__ float val_of(unsigned int k) {
    return __uint_as_float((k & 0x80000000u) ? (k ^ 0x80000000u) : ~k);
}

// ---------------------------------------------------------------------------
// Kernel 1: one block per row, single-pass logsumexp loss (90.6%-of-HBM
// mainloop, untouched). Tail: key write + one scattered histogram atomic.
// ---------------------------------------------------------------------------
__global__ __launch_bounds__(THREADS) void loss_kernel(const float* __restrict__ x,
                                                       const int* __restrict__ tgt) {
    const int row = blockIdx.x;
    const float4* __restrict__ rp =
        reinterpret_cast<const float4*>(x + (size_t)row * N_COLS);

    float s0 = 0.f, s1 = 0.f, s2 = 0.f, s3 = 0.f;

    int i = threadIdx.x;
    for (; i + 3 * THREADS < NV4; i += 4 * THREADS) {
        const float4 a = __ldcs(rp + i);
        const float4 b = __ldcs(rp + i + THREADS);
        const float4 c = __ldcs(rp + i + 2 * THREADS);
        const float4 d = __ldcs(rp + i + 3 * THREADS);
        s0 += (__expf(a.x) + __expf(a.y)) + (__expf(a.z) + __expf(a.w));
        s1 += (__expf(b.x) + __expf(b.y)) + (__expf(b.z) + __expf(b.w));
        s2 += (__expf(c.x) + __expf(c.y)) + (__expf(c.z) + __expf(c.w));
        s3 += (__expf(d.x) + __expf(d.y)) + (__expf(d.z) + __expf(d.w));
    }
    for (; i < NV4; i += THREADS) {
        const float4 a = __ldcs(rp + i);
        s0 += (__expf(a.x) + __expf(a.y)) + (__expf(a.z) + __expf(a.w));
    }

    float s = (s0 + s1) + (s2 + s3);
    #pragma unroll
    for (int off = 16; off; off >>= 1)
        s += __shfl_xor_sync(0xffffffffu, s, off);

    __shared__ float sm_s[THREADS / 32];
    const int warp = threadIdx.x >> 5;
    const int lane = threadIdx.x & 31;
    if (lane == 0) sm_s[warp] = s;
    __syncthreads();

    if (threadIdx.x == 0) {
        float t = 0.f;
        #pragma unroll
        for (int w = 0; w < THREADS / 32; w++) t += sm_s[w];
        const float loss = logf(t) - x[(size_t)row * N_COLS + tgt[row]];
        const unsigned int key = key_of(loss);
        g_keys[row] = key;
        atomicAdd(&g_hist[key >> (32 - HBITS)], 1u);
    }
}

// ---------------------------------------------------------------------------
// Kernel 2: one block, 1024 threads.
//  S1: scan 8192-bin histogram (zero-as-read) -> 13-bit prefix, rank rem.
//  S2: ONE sweep of keys: sum strictly-higher bins + compact selected bin
//      candidates to smem (capacity 8192: exact in the worst case).
//  S3: 3 radix passes (7/6/6 bits) over candidates, all in smem -> exact T.
//  S4: tie-exact mean of top-K2.
// ---------------------------------------------------------------------------
__global__ __launch_bounds__(1024) void select_mean_kernel(float* __restrict__ out) {
    const int tid = threadIdx.x;
    const int wid = tid >> 5;
    const int lane = tid & 31;

    __shared__ unsigned int cand[N_ROWS];     // 32 KB candidate list
    __shared__ unsigned int h2[128 * 4];      // radix hist, 4 spread copies
    __shared__ unsigned int warp_tot[32];
    __shared__ unsigned int warp_off[32];
    __shared__ unsigned int sel[2];           // [0]=digit  [1]=new rem
    __shared__ unsigned int sh_C;
    __shared__ double dacc[32];
    __shared__ unsigned int dcnt[32];

    // ---- Stage 1: suffix scan of 8192-bin histogram (descending) ----
    unsigned int selbin, rem;
    {
        if (tid == 0) sh_C = 0u;
        unsigned int hv[8], csum = 0u;
        const int base = NBINS - 1 - tid * 8;
        #pragma unroll
        for (int j = 0; j < 8; j++) {
            hv[j] = g_hist[base - j];
            g_hist[base - j] = 0u;            // restore for next graph replay
            csum += hv[j];
        }
        unsigned int pre = csum;
        #pragma unroll
        for (int off = 1; off < 32; off <<= 1) {
            const unsigned int v = __shfl_up_sync(0xffffffffu, pre, off);
            if (lane >= off) pre += v;
        }
        if (lane == 31) warp_tot[wid] = pre;
        __syncthreads();
        if (wid == 0) {                       // warp 0 scans the 32 warp totals
            unsigned int wv = warp_tot[lane];
            unsigned int wpre = wv;
            #pragma unroll
            for (int off = 1; off < 32; off <<= 1) {
                const unsigned int v = __shfl_up_sync(0xffffffffu, wpre, off);
                if (lane >= off) wpre += v;
            }
            warp_off[lane] = wpre - wv;       // exclusive
        }
        __syncthreads();
        unsigned int IS = warp_off[wid] + (pre - csum);
        #pragma unroll
        for (int j = 0; j < 8; j++) {
            const unsigned int lo = IS;
            IS += hv[j];
            if (IS >= K2 && lo < K2) { sel[0] = (unsigned)(base - j); sel[1] = K2 - lo; }
        }
        __syncthreads();
        selbin = sel[0];
        rem = sel[1];                         // ranks needed inside selbin
    }
    const unsigned int cnt_above = K2 - rem;  // keys in strictly higher bins

    // ---- Stage 2: single key sweep: sum higher bins + compact candidates ----
    double acc = 0.0;
    #pragma unroll
    for (int j = 0; j < 8; j++) {
        const unsigned int k = g_keys[j * 1024 + tid];
        const unsigned int b = k >> (32 - HBITS);
        if (b > selbin) acc += (double)val_of(k);
        else if (b == selbin) cand[atomicAdd(&sh_C, 1u)] = k;
    }
    __syncthreads();
    const unsigned int C = sh_C;              // rem <= C (guaranteed by S1)

    // ---- Stage 3: radix refine the remaining 19 bits over smem candidates ----
    unsigned int prefix = selbin << (32 - HBITS);
    const int shifts[3] = {12, 6, 0};
    const int widths[3] = {7, 6, 6};
    #pragma unroll
    for (int p = 0; p < 3; p++) {
        const int shift = shifts[p];
        const int nb = 1 << widths[p];
        h2[tid & 511] = 0u;                   // zero 512 words (first 512 thr enough)
        __syncthreads();
        const unsigned int mask = ~((1u << (shift + widths[p])) - 1u);
        const int spread = tid & 3;
        for (unsigned int i = tid; i < C; i += 1024) {
            const unsigned int k = cand[i];
            if ((k & mask) == prefix)
                atomicAdd(&h2[(((k >> shift) & (nb - 1)) << 2) + spread], 1u);
        }
        __syncthreads();
        if (wid == 0) {                       // warp 0: descending scan of nb bins
            const int chunk = nb >> 5;        // 4 or 2 bins per lane
            unsigned int hv2[4], cs = 0u;
            #pragma unroll 4
            for (int j = 0; j < chunk; j++) {
                const int b = nb - 1 - lane * chunk - j;
                hv2[j] = h2[(b << 2)] + h2[(b << 2) + 1] +
                         h2[(b << 2) + 2] + h2[(b << 2) + 3];
                cs += hv2[j];
            }
            unsigned int pre2 = cs;
            #pragma unroll
            for (int off = 1; off < 32; off <<= 1) {
                const unsigned int v = __shfl_up_sync(0xffffffffu, pre2, off);
                if (lane >= off) pre2 += v;
            }
            unsigned int IS2 = pre2 - cs;
            #pragma unroll 4
            for (int j = 0; j < chunk; j++) {
                const unsigned int lo = IS2;
                IS2 += hv2[j];
                if (IS2 >= rem && lo < rem) {
                    sel[0] = (unsigned)(nb - 1 - lane * chunk - j);
                    sel[1] = rem - lo;
                }
            }
        }
        __syncthreads();
        prefix |= sel[0] << (unsigned)shift;
        rem = sel[1];
        __syncthreads();                      // protect sel before next pass
    }
    const unsigned int T = prefix;            // exact key of the K2-th largest

    // ---- Stage 4: tie-exact mean ----
    unsigned int cntgt = 0u;
    for (unsigned int i = tid; i < C; i += 1024) {
        const unsigned int k = cand[i];
        if (k > T) { acc += (double)val_of(k); cntgt++; }
    }
    #pragma unroll
    for (int off = 16; off; off >>= 1) {
        acc += __shfl_down_sync(0xffffffffu, acc, off);
        cntgt += __shfl_down_sync(0xffffffffu, cntgt, off);
    }
    if (lane == 0) { dacc[wid] = acc; dcnt[wid] = cntgt; }
    __syncthreads();

    if (tid == 0) {
        double tsum = 0.0;
        unsigned int tgt_cnt = cnt_above;
        #pragma unroll
        for (int w = 0; w < 32; w++) { tsum += dacc[w]; tgt_cnt += dcnt[w]; }
        tsum += (double)(K2 - tgt_cnt) * (double)val_of(T);   // threshold ties
        out[0] = (float)(tsum / (double)K2);
    }
}

// ---------------------------------------------------------------------------
extern "C" void kernel_launch(void* const* d_in, const int* in_sizes, int n_in,
                              void* d_out, int out_size) {
    const float* x   = (const float*)d_in[0];
    const int*   tgt = (const int*)d_in[1];
    float*       out = (float*)d_out;

    loss_kernel<<<N_ROWS, THREADS>>>(x, tgt);
    select_mean_kernel<<<1, 1024>>>(out);
}

// round 15
// speedup vs baseline: 1.0339x; 1.0339x over previous
#include <cuda_runtime.h>

#define N_ROWS  8192
#define N_COLS  32000
#define NV4     (N_COLS / 4)
#define K2      4915              // int(0.6 * int(1.0 * 8192))
#define THREADS 256
#define NFINE   65536
#define QSCALE  2048.0f
#define NB2B    32                // finish-kernel blocks (256 thr each = 8192)

// Scratch (device globals; all counters restored each replay by the kernels)
__device__ float              g_vals[N_ROWS];
__device__ unsigned int       g_fine[NFINE];      // 256 KB fine histogram
__device__ unsigned int       g_coarse[256];
__device__ unsigned int       g_selbin;
__device__ unsigned int       g_rem;
__device__ unsigned long long g_sum;              // fixed-point 2^32 sum above bin
__device__ float              g_cand[N_ROWS];
__device__ unsigned int       g_candcnt;
__device__ unsigned int       g_done;

__device__ __forceinline__ int quant(float v) {
    int q = (int)(v * QSCALE);
    return max(0, min(q, NFINE - 1));
}
__device__ __forceinline__ unsigned int key_of(float f) {
    unsigned int u = __float_as_uint(f);
    return u ^ ((u & 0x80000000u) ? 0xFFFFFFFFu : 0x80000000u);
}
__device__ __forceinline__ float val_of(unsigned int k) {
    return __uint_as_float((k & 0x80000000u) ? (k ^ 0x80000000u) : ~k);
}
__device__ __forceinline__ long long fixed_of(float v) {
    return (long long)((double)v * 4294967296.0);   // exact, deterministic
}

// ---------------------------------------------------------------------------
// Kernel 1: one block per row, single-pass logsumexp loss (proven mainloop).
// Tail: store loss + fine/coarse histogram atomics (distributed, free).
// ---------------------------------------------------------------------------
__global__ __launch_bounds__(THREADS) void loss_kernel(const float* __restrict__ x,
                                                       const int* __restrict__ tgt) {
    const int row = blockIdx.x;
    const float4* __restrict__ rp =
        reinterpret_cast<const float4*>(x + (size_t)row * N_COLS);

    float s0 = 0.f, s1 = 0.f, s2 = 0.f, s3 = 0.f;
    int i = threadIdx.x;
    for (; i + 3 * THREADS < NV4; i += 4 * THREADS) {
        const float4 a = __ldcs(rp + i);
        const float4 b = __ldcs(rp + i + THREADS);
        const float4 c = __ldcs(rp + i + 2 * THREADS);
        const float4 d = __ldcs(rp + i + 3 * THREADS);
        s0 += (__expf(a.x) + __expf(a.y)) + (__expf(a.z) + __expf(a.w));
        s1 += (__expf(b.x) + __expf(b.y)) + (__expf(b.z) + __expf(b.w));
        s2 += (__expf(c.x) + __expf(c.y)) + (__expf(c.z) + __expf(c.w));
        s3 += (__expf(d.x) + __expf(d.y)) + (__expf(d.z) + __expf(d.w));
    }
    for (; i < NV4; i += THREADS) {
        const float4 a = __ldcs(rp + i);
        s0 += (__expf(a.x) + __expf(a.y)) + (__expf(a.z) + __expf(a.w));
    }

    float s = (s0 + s1) + (s2 + s3);
    #pragma unroll
    for (int off = 16; off; off >>= 1)
        s += __shfl_xor_sync(0xffffffffu, s, off);

    __shared__ float sm_s[THREADS / 32];
    const int warp = threadIdx.x >> 5;
    const int lane = threadIdx.x & 31;
    if (lane == 0) sm_s[warp] = s;
    __syncthreads();

    if (threadIdx.x == 0) {
        float t = 0.f;
        #pragma unroll
        for (int w = 0; w < THREADS / 32; w++) t += sm_s[w];
        const float loss = logf(t) - x[(size_t)row * N_COLS + tgt[row]];
        g_vals[row] = loss;
        const int q = quant(loss);
        atomicAdd(&g_fine[q], 1u);
        atomicAdd(&g_coarse[q >> 8], 1u);
    }
}

// ---------------------------------------------------------------------------
// Kernel 2a: 1 block, 256 threads. Coarse scan (256 bins) -> fine scan of one
// 256-bin stripe -> exact selbin + rank rem. Zeroes coarse as read.
// ---------------------------------------------------------------------------
__global__ __launch_bounds__(256) void scan_kernel() {
    const int tid = threadIdx.x;
    const int wid = tid >> 5;
    const int lane = tid & 31;

    __shared__ unsigned int wtot[8], woff[8];
    __shared__ unsigned int sel2[2];

    // ---- coarse scan (descending bins: thread t owns bin 255-t) ----
    unsigned int v = g_coarse[255 - tid];
    g_coarse[255 - tid] = 0u;                  // restore for next replay
    unsigned int pre = v;
    #pragma unroll
    for (int off = 1; off < 32; off <<= 1) {
        const unsigned int u = __shfl_up_sync(0xffffffffu, pre, off);
        if (lane >= off) pre += u;
    }
    if (lane == 31) wtot[wid] = pre;
    __syncthreads();
    if (tid == 0) {
        unsigned int a = 0;
        #pragma unroll
        for (int w = 0; w < 8; w++) { woff[w] = a; a += wtot[w]; }
    }
    __syncthreads();
    unsigned int excl = woff[wid] + (pre - v); // count of keys in bins > mine
    if (excl < K2 && excl + v >= K2) {
        sel2[0] = (unsigned)(255 - tid);
        sel2[1] = K2 - excl;
    }
    __syncthreads();
    const unsigned int cb = sel2[0];
    const unsigned int remc = sel2[1];
    __syncthreads();                            // protect sel2 before reuse

    // ---- fine scan inside coarse bin cb ----
    v = g_fine[cb * 256 + 255 - tid];           // zeroing done by finish kernel
    pre = v;
    #pragma unroll
    for (int off = 1; off < 32; off <<= 1) {
        const unsigned int u = __shfl_up_sync(0xffffffffu, pre, off);
        if (lane >= off) pre += u;
    }
    if (lane == 31) wtot[wid] = pre;
    __syncthreads();
    if (tid == 0) {
        unsigned int a = 0;
        #pragma unroll
        for (int w = 0; w < 8; w++) { woff[w] = a; a += wtot[w]; }
    }
    __syncthreads();
    excl = woff[wid] + (pre - v);
    if (excl < remc && excl + v >= remc) {
        sel2[0] = (unsigned)(255 - tid);
        sel2[1] = remc - excl;
    }
    __syncthreads();
    if (tid == 0) {
        g_selbin = cb * 256 + sel2[0];
        g_rem = sel2[1];
    }
}

// ---------------------------------------------------------------------------
// Kernel 2b: 32 blocks x 256 threads (whole chip). One key/thread:
//  q > selbin -> fixed-point int64 block-sum -> one global atomic (exact).
//  q == selbin -> compact to global candidate list (tiny set).
// Each block zeroes its 2048-bin fine-hist slice. Last block (done-counter)
// radix-selects top-rem among candidates in smem and writes the mean.
// ---------------------------------------------------------------------------
__global__ __launch_bounds__(256) void finish_kernel(float* __restrict__ out) {
    const int tid = threadIdx.x;
    const int bid = blockIdx.x;
    const int wid = tid >> 5;
    const int lane = tid & 31;

    const unsigned int selbin = g_selbin;
    const unsigned int rem = g_rem;

    const float v = g_vals[bid * 256 + tid];
    const int q = quant(v);
    long long loc = 0;
    if ((unsigned)q > selbin) loc = fixed_of(v);
    else if ((unsigned)q == selbin) g_cand[atomicAdd(&g_candcnt, 1u)] = v;

    // block reduce int64
    #pragma unroll
    for (int off = 16; off; off >>= 1)
        loc += __shfl_down_sync(0xffffffffu, loc, off);
    __shared__ long long wsum[8];
    if (lane == 0) wsum[wid] = loc;
    __syncthreads();
    if (tid == 0) {
        long long s = 0;
        #pragma unroll
        for (int w = 0; w < 8; w++) s += wsum[w];
        atomicAdd(&g_sum, (unsigned long long)s);
    }

    // zero this block's fine-hist slice (replay determinism)
    #pragma unroll
    for (int j = 0; j < 2048 / 256; j++)
        g_fine[bid * 2048 + j * 256 + tid] = 0u;

    __threadfence();
    __shared__ unsigned int sh_last;
    if (tid == 0)
        sh_last = (atomicAdd(&g_done, 1u) == (unsigned)(NB2B - 1)) ? 1u : 0u;
    __syncthreads();
    if (!sh_last) return;

    // ---------------- last block: finish ----------------
    __threadfence();
    const unsigned int C = *(volatile unsigned int*)&g_candcnt;   // >= rem

    __shared__ unsigned int skey[N_ROWS];   // 32 KB, worst-case capacity
    __shared__ unsigned int h2[256 * 4];
    __shared__ unsigned int sel2[2];
    for (unsigned int j = tid; j < C; j += 256) skey[j] = key_of(g_cand[j]);
    __syncthreads();

    // 4 x 8-bit MSB-first radix-select of the rem-th largest candidate
    unsigned int prefix = 0u, r = rem;
    #pragma unroll
    for (int shift = 24; shift >= 0; shift -= 8) {
        h2[tid] = 0u; h2[tid + 256] = 0u; h2[tid + 512] = 0u; h2[tid + 768] = 0u;
        __syncthreads();
        const unsigned int mask =
            (shift == 24) ? 0u : (0xFFFFFFFFu << (unsigned)(shift + 8));
        const int spread = tid & 3;
        for (unsigned int j = tid; j < C; j += 256) {
            const unsigned int k = skey[j];
            if ((k & mask) == prefix)
                atomicAdd(&h2[(((k >> shift) & 255u) << 2) + spread], 1u);
        }
        __syncthreads();
        if (wid == 0) {                      // descending scan, 8 bins/lane
            unsigned int hv[8], cs = 0u;
            #pragma unroll
            for (int j = 0; j < 8; j++) {
                const int b = 255 - lane * 8 - j;
                hv[j] = h2[(b << 2)] + h2[(b << 2) + 1] +
                        h2[(b << 2) + 2] + h2[(b << 2) + 3];
                cs += hv[j];
            }
            unsigned int pre2 = cs;
            #pragma unroll
            for (int off = 1; off < 32; off <<= 1) {
                const unsigned int u = __shfl_up_sync(0xffffffffu, pre2, off);
                if (lane >= off) pre2 += u;
            }
            unsigned int IS = pre2 - cs;
            #pragma unroll
            for (int j = 0; j < 8; j++) {
                const unsigned int lo = IS;
                IS += hv[j];
                if (IS >= r && lo < r) {
                    sel2[0] = (unsigned)(255 - lane * 8 - j);
                    sel2[1] = r - lo;
                }
            }
        }
        __syncthreads();
        prefix |= sel2[0] << (unsigned)shift;
        r = sel2[1];
        __syncthreads();
    }
    const unsigned int T = prefix;

    // tie-exact candidate sum
    long long acc = 0; unsigned int cg = 0;
    for (unsigned int j = tid; j < C; j += 256) {
        const unsigned int k = skey[j];
        if (k > T) { acc += fixed_of(val_of(k)); cg++; }
    }
    #pragma unroll
    for (int off = 16; off; off >>= 1) {
        acc += __shfl_down_sync(0xffffffffu, acc, off);
        cg  += __shfl_down_sync(0xffffffffu, cg, off);
    }
    __shared__ long long fsum[8];
    __shared__ unsigned int fcnt[8];
    if (lane == 0) { fsum[wid] = acc; fcnt[wid] = cg; }
    __syncthreads();

    if (tid == 0) {
        long long csum = 0; unsigned int ccnt = 0;
        #pragma unroll
        for (int w = 0; w < 8; w++) { csum += fsum[w]; ccnt += fcnt[w]; }
        const long long above = (long long)(*(volatile unsigned long long*)&g_sum);
        const long long total = above + csum +
            (long long)(rem - ccnt) * fixed_of(val_of(T));
        out[0] = (float)((double)total / 4294967296.0 / (double)K2);
        // restore replay state
        g_candcnt = 0u;
        g_done = 0u;
        g_sum = 0ull;
    }
}

// ---------------------------------------------------------------------------
extern "C" void kernel_launch(void* const* d_in, const int* in_sizes, int n_in,
                              void* d_out, int out_size) {
    const float* x   = (const float*)d_in[0];
    const int*   tgt = (const int*)d_in[1];
    float*       out = (float*)d_out;

    loss_kernel<<<N_ROWS, THREADS>>>(x, tgt);
    scan_kernel<<<1, 256>>>();
    finish_kernel<<<NB2B, 256>>>(out);
}